// round 15
// baseline (speedup 1.0000x reference)
#include <cuda_runtime.h>
#include <cuda_fp16.h>
#include <cstdint>
#include <cstddef>

// Problem constants (fixed by the dataset)
#define NU_MAX 100000
#define NI_MAX 50000
#define E_MAX 300000
#define DD 128
#define PAD_ROWS 256
#define SCAN_B 1024

// ---------------- device scratch (no allocations allowed) ----------------
__device__ __align__(16) __half g_xh_u[(size_t)(NU_MAX + PAD_ROWS) * DD];
__device__ __align__(16) __half g_xh_i[(size_t)(NI_MAX + PAD_ROWS) * DD];
__device__ __align__(16) __half g_h1h_u[(size_t)(NU_MAX + PAD_ROWS) * DD];
__device__ __align__(16) __half g_h1h_i[(size_t)(NI_MAX + PAD_ROWS) * DD];
__device__ int g_deg[NU_MAX + NI_MAX];   // [0,NU): user deg; [NU,NU+NI): item deg
__device__ int g_off[NU_MAX + NI_MAX];
__device__ int g_cur[NU_MAX + NI_MAX];
__device__ int g_bsum[256];
__device__ int g_adj_u[E_MAX];
__device__ int g_adj_i[E_MAX];
// fp16 weights, 4 cfgs. Per cfg: [32 kb][128 n][8 k] fp16 = 32768 fp16.
__device__ __align__(16) __half g_wtb[4 * 32768];

// ---------------- weight prep: all 4 cfgs in one launch ----------------
__global__ void prep_weights4(const float* __restrict__ Wr0, const float* __restrict__ LW0,
                              const float* __restrict__ Wl0,
                              const float* __restrict__ Wr1, const float* __restrict__ LW1,
                              const float* __restrict__ Wl1,
                              const float* __restrict__ Wr2, const float* __restrict__ LW2,
                              const float* __restrict__ Wl2,
                              const float* __restrict__ Wr3, const float* __restrict__ LW3,
                              const float* __restrict__ Wl3,
                              __half* __restrict__ dst_base) {
    int cfg = blockIdx.x >> 5;
    int kb = blockIdx.x & 31;
    const float* Wr; const float* LW; const float* Wl;
    if (cfg == 0)      { Wr = Wr0; LW = LW0; Wl = Wl0; }
    else if (cfg == 1) { Wr = Wr1; LW = LW1; Wl = Wl1; }
    else if (cfg == 2) { Wr = Wr2; LW = LW2; Wl = Wl2; }
    else               { Wr = Wr3; LW = LW3; Wl = Wl3; }
    __half* dst = dst_base + cfg * 32768;
    int t = threadIdx.x;
#pragma unroll
    for (int i = 0; i < 4; ++i) {
        int e = i * 256 + t;
        int n = e >> 3, kd = e & 7;
        int k = kb * 8 + kd;
        float v;
        if (k < 128) v = Wr[n * 128 + k] + LW[n * 128 + k];
        else         v = Wl[n * 128 + (k - 128)];
        dst[kb * 1024 + e] = __float2half_rn(v);
    }
}

// ---------------- fp32 -> fp16 table conversion ----------------
__global__ void conv_fp16_2(const float* __restrict__ A, __half* __restrict__ HA, int nA,
                            const float* __restrict__ B, __half* __restrict__ HB, int nB) {
    int i = (blockIdx.x * blockDim.x + threadIdx.x) * 8;
    const float* src; __half* dst;
    if (i < nA) { src = A + i; dst = HA + i; }
    else {
        i -= nA;
        if (i >= nB) return;
        src = B + i; dst = HB + i;
    }
    float4 v0 = *(const float4*)(src);
    float4 v1 = *(const float4*)(src + 4);
    __half2 h0 = __floats2half2_rn(v0.x, v0.y);
    __half2 h1 = __floats2half2_rn(v0.z, v0.w);
    __half2 h2 = __floats2half2_rn(v1.x, v1.y);
    __half2 h3 = __floats2half2_rn(v1.z, v1.w);
    *(uint4*)(dst) = make_uint4(*(uint32_t*)&h0, *(uint32_t*)&h1,
                                *(uint32_t*)&h2, *(uint32_t*)&h3);
}

// ---------------- CSR build (parallel scan; merged deg array) --------------
__global__ void count_deg(const int* __restrict__ iu_dst, const int* __restrict__ ui_dst,
                          int E, int nU, int* __restrict__ deg) {
    int i = blockIdx.x * blockDim.x + threadIdx.x;
    if (i < E) atomicAdd(deg + iu_dst[i], 1);
    else { i -= E; if (i < E) atomicAdd(deg + nU + ui_dst[i], 1); }
}

__global__ void scan_part(const int* __restrict__ deg, int nU, int nI,
                          int* __restrict__ off, int* __restrict__ bsum, int nbU) {
    __shared__ int warp_s[32];
    int b = blockIdx.x;
    int segbase, n, idx0;
    if (b < nbU) { segbase = 0; n = nU; idx0 = b * SCAN_B; }
    else         { segbase = nU; n = nI; idx0 = (b - nbU) * SCAN_B; }
    int i = idx0 + threadIdx.x;
    int v = (i < n) ? deg[segbase + i] : 0;
    int lane = threadIdx.x & 31, wrp = threadIdx.x >> 5;
    int inc = v;
#pragma unroll
    for (int o = 1; o < 32; o <<= 1) {
        int t = __shfl_up_sync(0xffffffffu, inc, o);
        if (lane >= o) inc += t;
    }
    if (lane == 31) warp_s[wrp] = inc;
    __syncthreads();
    if (wrp == 0) {
        int wv = warp_s[lane];
#pragma unroll
        for (int o = 1; o < 32; o <<= 1) {
            int t = __shfl_up_sync(0xffffffffu, wv, o);
            if (lane >= o) wv += t;
        }
        warp_s[lane] = wv;
    }
    __syncthreads();
    int base = (wrp > 0) ? warp_s[wrp - 1] : 0;
    int excl = base + inc - v;
    if (i < n) off[segbase + i] = excl;
    if (threadIdx.x == SCAN_B - 1) bsum[b] = base + inc;
}

__global__ void scan_top(int* __restrict__ bsum, int nbU, int nbI) {
    __shared__ int s[256];
    int t = threadIdx.x;
    int ntot = nbU + nbI;
    if (t < ntot) s[t] = bsum[t];
    __syncthreads();
    if (t == 0) {
        int acc = 0;
        for (int i = 0; i < nbU; ++i) { int tmp = s[i]; s[i] = acc; acc += tmp; }
    }
    if (t == 1) {
        int acc = 0;
        for (int i = nbU; i < ntot; ++i) { int tmp = s[i]; s[i] = acc; acc += tmp; }
    }
    __syncthreads();
    if (t < ntot) bsum[t] = s[t];
}

__global__ void scan_add(int* __restrict__ off, int* __restrict__ cur,
                         int nU, int nI, const int* __restrict__ bsum, int nbU) {
    int i = blockIdx.x * blockDim.x + threadIdx.x;
    int nTot = nU + nI;
    if (i >= nTot) return;
    int blk = (i < nU) ? (i / SCAN_B) : (nbU + (i - nU) / SCAN_B);
    int v = off[i] + bsum[blk];
    off[i] = v;
    cur[i] = v;
}

__global__ void fill_adj(const int* __restrict__ iu_src, const int* __restrict__ iu_dst,
                         const int* __restrict__ ui_src, const int* __restrict__ ui_dst,
                         int E, int nU, int* __restrict__ cur,
                         int* __restrict__ adjU, int* __restrict__ adjI) {
    int i = blockIdx.x * blockDim.x + threadIdx.x;
    if (i < E) {
        int p = atomicAdd(cur + iu_dst[i], 1);
        adjU[p] = iu_src[i];
    } else {
        i -= E;
        if (i < E) {
            int p = atomicAdd(cur + nU + ui_dst[i], 1);
            adjI[p] = ui_src[i];
        }
    }
}

// ---------------- fused SAGE GEMM: in-kernel mean gather + fp16 MMA --------
// out[m,:] = act( X[m,:] @ Wc^T + mean_{s in N(m)} F[s,:] @ Wl^T + b1 + b2 )
__device__ __forceinline__ void ldsm4(uint32_t* r, const void* p) {
    uint32_t a = (uint32_t)__cvta_generic_to_shared(p);
    asm volatile("ldmatrix.sync.aligned.m8n8.x4.shared.b16 {%0,%1,%2,%3}, [%4];\n"
                 : "=r"(r[0]), "=r"(r[1]), "=r"(r[2]), "=r"(r[3]) : "r"(a));
}
__device__ __forceinline__ void mma16816(float* c, const uint32_t* a, const uint32_t* b) {
    asm volatile("mma.sync.aligned.m16n8k16.row.col.f32.f16.f16.f32 "
                 "{%0,%1,%2,%3}, {%4,%5,%6,%7}, {%8,%9}, {%0,%1,%2,%3};\n"
                 : "+f"(c[0]), "+f"(c[1]), "+f"(c[2]), "+f"(c[3])
                 : "r"(a[0]), "r"(a[1]), "r"(a[2]), "r"(a[3]), "r"(b[0]), "r"(b[1]));
}
__device__ __forceinline__ void cp_async16(void* smem_dst, const void* gsrc) {
    uint32_t a = (uint32_t)__cvta_generic_to_shared(smem_dst);
    asm volatile("cp.async.cg.shared.global [%0], [%1], 16;\n"
                 :: "r"(a), "l"(gsrc) : "memory");
}
#define CP_ASYNC_COMMIT() asm volatile("cp.async.commit_group;\n" ::: "memory")
#define CP_ASYNC_WAIT0()  asm volatile("cp.async.wait_group 0;\n" ::: "memory")

// smem map (bytes):
//   0:      W stages  2 x 8192  = 16384
//   16384:  A stages  2 x 16384 = 32768   (chunks 0-3 only, X side)
//   49152:  mean buf  4 x 16384 = 65536   (chunks 4-7, ldsm-ready layout)
//   114688: bss 128 f32
#define SM_BYTES 115200

__global__ __launch_bounds__(512, 1)
void sage_gemm_fused(const __half* __restrict__ Xh0, const __half* __restrict__ F0,
                     const int* __restrict__ adj0, const __half* __restrict__ Wt0,
                     const float* __restrict__ b1_0, const float* __restrict__ b2_0,
                     float* __restrict__ out0, __half* __restrict__ outh0, int n0, int split,
                     const __half* __restrict__ Xh1, const __half* __restrict__ F1,
                     const int* __restrict__ adj1, const __half* __restrict__ Wt1,
                     const float* __restrict__ b1_1, const float* __restrict__ b2_1,
                     float* __restrict__ out1, __half* __restrict__ outh1, int n1,
                     const int* __restrict__ off, const int* __restrict__ deg,
                     int nU, int do_relu) {
    extern __shared__ char sm_raw[];
    __half* Wsm = (__half*)sm_raw;                    // 2 stages x 4096 halves
    __half* Asm = (__half*)(sm_raw + 16384);          // 2 stages x 8192 halves
    __half* Msm = (__half*)(sm_raw + 49152);          // 4 chunk tiles x 8192 halves
    float* bss = (float*)(sm_raw + 114688);

    const __half* Xh; const __half* F; const int* adj; const __half* Wt;
    const float* b1; const float* b2; float* out; __half* outh;
    int nrows, bidx, oib;
    if ((int)blockIdx.x < split) {
        Xh = Xh0; F = F0; adj = adj0; Wt = Wt0; b1 = b1_0; b2 = b2_0;
        out = out0; outh = outh0; nrows = n0; bidx = blockIdx.x; oib = 0;
    } else {
        Xh = Xh1; F = F1; adj = adj1; Wt = Wt1; b1 = b1_1; b2 = b2_1;
        out = out1; outh = outh1; nrows = n1; bidx = blockIdx.x - split; oib = nU;
    }

    const int tid = threadIdx.x;
    const int lane = tid & 31;
    const int wid = tid >> 5;
    const int m0w = (wid & 3) * 64;    // warp m-origin (64-row warp tile)
    const int n0w = (wid >> 2) * 32;   // warp n-origin
    const int m0 = bidx * 256;

    const int sel = lane >> 3, lr = lane & 7;
    const int a_ro = ((sel & 1) << 3) + lr;
    const int a_kb = sel >> 1;
    const int b_ro = ((sel >> 1) << 3) + lr;
    const int b_kb = sel & 1;

    if (tid < 128) bss[tid] = b1[tid] + b2[tid];

    // W chunk c -> stage st (8 KB; 512 thr x 16 B)
    auto loadW = [&](int c, int st) {
        const char* sh = (const char*)(Wt + c * 4096) + tid * 16;
        char* dh = (char*)(Wsm + st * 4096) + tid * 16;
        cp_async16(dh, sh);
    };
    // X chunk c (0..3) -> stage st: 16 KB, block layout [kb 4][row 256][8 k]
    auto loadA = [&](int c, int st) {
#pragma unroll
        for (int h = 0; h < 2; ++h) {
            int p = tid + h * 512;          // 0..1023
            int kb = p >> 8, row = p & 255;
            const char* s = (const char*)(Xh + (size_t)(m0 + row) * DD)
                            + c * 64 + kb * 16;
            char* d = (char*)(Asm + st * 8192) + p * 16;
            cp_async16(d, s);
        }
    };

    // prologue loads (latency hidden under the mean gather below)
    loadW(0, 0);
    loadA(0, 0);
    CP_ASYNC_COMMIT();

    // ---- in-kernel mean gather: 32 half-warp groups x 8 rows each ----
    {
        int gg = tid >> 4, l16 = tid & 15;
        for (int rr = gg; rr < 256; rr += 32) {
            int row = m0 + rr;
            float4 a0 = make_float4(0.f, 0.f, 0.f, 0.f);
            float4 b0 = make_float4(0.f, 0.f, 0.f, 0.f);
            float4 a1 = make_float4(0.f, 0.f, 0.f, 0.f);
            float4 b1v = make_float4(0.f, 0.f, 0.f, 0.f);
            if (row < nrows) {
                int oidx = oib + row;
                int beg = __ldg(off + oidx);
                int dg = __ldg(deg + oidx);
                int end = beg + dg;
                auto addrow = [&](int s, float4& accA, float4& accB) {
                    uint4 u = *(const uint4*)(F + (size_t)s * DD + l16 * 8);
                    float2 f0 = __half22float2(*(__half2*)&u.x);
                    float2 f1 = __half22float2(*(__half2*)&u.y);
                    float2 f2 = __half22float2(*(__half2*)&u.z);
                    float2 f3 = __half22float2(*(__half2*)&u.w);
                    accA.x += f0.x; accA.y += f0.y; accA.z += f1.x; accA.w += f1.y;
                    accB.x += f2.x; accB.y += f2.y; accB.z += f3.x; accB.w += f3.y;
                };
                int base = beg;
                for (; base + 4 <= end; base += 4) {
                    int s0 = __ldg(adj + base + 0);
                    int s1 = __ldg(adj + base + 1);
                    int s2 = __ldg(adj + base + 2);
                    int s3 = __ldg(adj + base + 3);
                    addrow(s0, a0, b0); addrow(s1, a1, b1v);
                    addrow(s2, a0, b0); addrow(s3, a1, b1v);
                }
                for (; base < end; ++base) addrow(__ldg(adj + base), a0, b0);
                float inv = 1.0f / (float)max(dg, 1);
                a0.x = (a0.x + a1.x) * inv; a0.y = (a0.y + a1.y) * inv;
                a0.z = (a0.z + a1.z) * inv; a0.w = (a0.w + a1.w) * inv;
                b0.x = (b0.x + b1v.x) * inv; b0.y = (b0.y + b1v.y) * inv;
                b0.z = (b0.z + b1v.z) * inv; b0.w = (b0.w + b1v.w) * inv;
            }
            __half2 o0 = __floats2half2_rn(a0.x, a0.y);
            __half2 o1 = __floats2half2_rn(a0.z, a0.w);
            __half2 o2 = __floats2half2_rn(b0.x, b0.y);
            __half2 o3 = __floats2half2_rn(b0.z, b0.w);
            int col = l16 * 8;
            int ch = col >> 5, kb = (col >> 3) & 3;
            *(uint4*)(Msm + ch * 8192 + (kb * 256 + rr) * 8) =
                make_uint4(*(uint32_t*)&o0, *(uint32_t*)&o1,
                           *(uint32_t*)&o2, *(uint32_t*)&o3);
        }
    }

    float acc[4][4][4];
#pragma unroll
    for (int i = 0; i < 4; ++i)
#pragma unroll
        for (int j = 0; j < 4; ++j)
#pragma unroll
            for (int q = 0; q < 4; ++q) acc[i][j][q] = 0.f;

    CP_ASYNC_WAIT0();
    __syncthreads();

    for (int c = 0; c < 8; ++c) {
        int st = c & 1;
        if (c < 7) {
            loadW(c + 1, 1 - st);
            if (c + 1 < 4) loadA(c + 1, 1 - st);
            CP_ASYNC_COMMIT();
        }
        const __half* atile = (c < 4) ? (Asm + st * 8192) : (Msm + (c - 4) * 8192);
#pragma unroll
        for (int kk = 0; kk < 2; ++kk) {
            uint32_t ah[4][4], bh[2][4];
#pragma unroll
            for (int mt = 0; mt < 4; ++mt) {
                const __half* p = atile +
                    (((2 * kk + a_kb) * 256) + m0w + mt * 16 + a_ro) * 8;
                ldsm4(ah[mt], p);
            }
#pragma unroll
            for (int ng = 0; ng < 2; ++ng) {
                const __half* p = Wsm + st * 4096 +
                    (((2 * kk + b_kb) * 128) + n0w + ng * 16 + b_ro) * 8;
                ldsm4(bh[ng], p);
            }
#pragma unroll
            for (int mt = 0; mt < 4; ++mt)
#pragma unroll
                for (int nt = 0; nt < 4; ++nt)
                    mma16816(acc[mt][nt], ah[mt], &bh[nt >> 1][(nt & 1) * 2]);
        }
        if (c < 7) {
            CP_ASYNC_WAIT0();
            __syncthreads();
        }
    }

    // epilogue: bias (+relu); layer-1 writes fp16 only, layer-2 fp32 only
#pragma unroll
    for (int mt = 0; mt < 4; ++mt) {
        int rbase = m0w + mt * 16 + (lane >> 2);
#pragma unroll
        for (int half = 0; half < 2; ++half) {
            int r = rbase + half * 8;
            if (m0 + r >= nrows) continue;
#pragma unroll
            for (int nt = 0; nt < 4; ++nt) {
                int col = n0w + nt * 8 + (lane & 3) * 2;
                float v0 = acc[mt][nt][half * 2 + 0] + bss[col];
                float v1 = acc[mt][nt][half * 2 + 1] + bss[col + 1];
                if (do_relu) {
                    v0 = fmaxf(v0, 0.f); v1 = fmaxf(v1, 0.f);
                    __half2 hv = __floats2half2_rn(v0, v1);
                    *(__half2*)(outh + (size_t)(m0 + r) * DD + col) = hv;
                } else {
                    *(float2*)(out + (size_t)(m0 + r) * DD + col) = make_float2(v0, v1);
                }
            }
        }
    }
}

// ---------------- host orchestration ----------------
extern "C" void kernel_launch(void* const* d_in, const int* in_sizes, int n_in,
                              void* d_out, int out_size) {
    const float* x_user = (const float*)d_in[0];
    const float* x_item = (const float*)d_in[1];
    const int* ui_src = (const int*)d_in[2];
    const int* ui_dst = (const int*)d_in[3];
    const int* iu_src = (const int*)d_in[4];
    const int* iu_dst = (const int*)d_in[5];
    const float* W1l_ui = (const float*)d_in[6];
    const float* b1_ui  = (const float*)d_in[7];
    const float* W1r_ui = (const float*)d_in[8];
    const float* W1l_iu = (const float*)d_in[9];
    const float* b1_iu  = (const float*)d_in[10];
    const float* W1r_iu = (const float*)d_in[11];
    const float* L1W_u  = (const float*)d_in[12];
    const float* L1b_u  = (const float*)d_in[13];
    const float* L1W_i  = (const float*)d_in[14];
    const float* L1b_i  = (const float*)d_in[15];
    const float* W2l_ui = (const float*)d_in[16];
    const float* b2_ui  = (const float*)d_in[17];
    const float* W2r_ui = (const float*)d_in[18];
    const float* W2l_iu = (const float*)d_in[19];
    const float* b2_iu  = (const float*)d_in[20];
    const float* W2r_iu = (const float*)d_in[21];
    const float* L2W_u  = (const float*)d_in[22];
    const float* L2b_u  = (const float*)d_in[23];
    const float* L2W_i  = (const float*)d_in[24];
    const float* L2b_i  = (const float*)d_in[25];

    const int NU = in_sizes[0] / DD;
    const int NI = in_sizes[1] / DD;
    const int E = in_sizes[2];

    __half *xh_u, *xh_i, *h1h_u, *h1h_i, *wtb;
    int *deg, *off, *cur, *bsum, *adj_u, *adj_i;
    cudaGetSymbolAddress((void**)&xh_u, g_xh_u);
    cudaGetSymbolAddress((void**)&xh_i, g_xh_i);
    cudaGetSymbolAddress((void**)&h1h_u, g_h1h_u);
    cudaGetSymbolAddress((void**)&h1h_i, g_h1h_i);
    cudaGetSymbolAddress((void**)&deg, g_deg);
    cudaGetSymbolAddress((void**)&off, g_off);
    cudaGetSymbolAddress((void**)&cur, g_cur);
    cudaGetSymbolAddress((void**)&bsum, g_bsum);
    cudaGetSymbolAddress((void**)&adj_u, g_adj_u);
    cudaGetSymbolAddress((void**)&adj_i, g_adj_i);
    cudaGetSymbolAddress((void**)&wtb, g_wtb);

    cudaFuncSetAttribute(sage_gemm_fused, cudaFuncAttributeMaxDynamicSharedMemorySize,
                         SM_BYTES);

    float* out_u = (float*)d_out;
    float* out_i = out_u + (size_t)NU * DD;

    // weight prep (fp16 block layout; one launch)
    prep_weights4<<<128, 256>>>(W1r_iu, L1W_u, W1l_iu,
                                W1r_ui, L1W_i, W1l_ui,
                                W2r_iu, L2W_u, W2l_iu,
                                W2r_ui, L2W_i, W2l_ui, wtb);

    // fp16 copies of input features
    {
        int nA = NU * DD, nB = NI * DD;
        int thr = (nA + nB) / 8;
        conv_fp16_2<<<(thr + 255) / 256, 256>>>(x_user, xh_u, nA, x_item, xh_i, nB);
    }

    // CSR build via parallel scan (merged deg array, two segments)
    int nTot = NU + NI;
    cudaMemsetAsync(deg, 0, nTot * sizeof(int));
    count_deg<<<(2 * E + 255) / 256, 256>>>(iu_dst, ui_dst, E, NU, deg);
    int nbU = (NU + SCAN_B - 1) / SCAN_B, nbI = (NI + SCAN_B - 1) / SCAN_B;
    scan_part<<<nbU + nbI, SCAN_B>>>(deg, NU, NI, off, bsum, nbU);
    scan_top<<<1, 256>>>(bsum, nbU, nbI);
    scan_add<<<(nTot + 255) / 256, 256>>>(off, cur, NU, NI, bsum, nbU);
    fill_adj<<<(2 * E + 255) / 256, 256>>>(iu_src, iu_dst, ui_src, ui_dst, E, NU,
                                           cur, adj_u, adj_i);

    int gu = (NU + 255) / 256, gi = (NI + 255) / 256;
    // layer 1: fused gather + GEMM (fp16 h1 output)
    sage_gemm_fused<<<gu + gi, 512, SM_BYTES>>>(
        xh_u, xh_i, adj_u, wtb + 0 * 32768, b1_iu, L1b_u, (float*)0, h1h_u, NU, gu,
        xh_i, xh_u, adj_i, wtb + 1 * 32768, b1_ui, L1b_i, (float*)0, h1h_i, NI,
        off, deg, NU, 1);

    // layer 2: fused gather + GEMM (fp32 output)
    sage_gemm_fused<<<gu + gi, 512, SM_BYTES>>>(
        h1h_u, h1h_i, adj_u, wtb + 2 * 32768, b2_iu, L2b_u, out_u, (__half*)0, NU, gu,
        h1h_i, h1h_u, adj_i, wtb + 3 * 32768, b2_ui, L2b_i, out_i, (__half*)0, NI,
        off, deg, NU, 0);
}

// round 17
// speedup vs baseline: 1.1114x; 1.1114x over previous
#include <cuda_runtime.h>
#include <cuda_fp16.h>
#include <cstdint>
#include <cstddef>

// Problem constants (fixed by the dataset)
#define NU_MAX 100000
#define NI_MAX 50000
#define E_MAX 300000
#define DD 128
#define PAD_ROWS 256
#define SCAN_B 1024

// ---------------- device scratch (no allocations allowed) ----------------
__device__ __align__(16) __half g_xh_u[(size_t)(NU_MAX + PAD_ROWS) * DD];
__device__ __align__(16) __half g_xh_i[(size_t)(NI_MAX + PAD_ROWS) * DD];
__device__ __align__(16) __half g_h1h_u[(size_t)(NU_MAX + PAD_ROWS) * DD];
__device__ __align__(16) __half g_h1h_i[(size_t)(NI_MAX + PAD_ROWS) * DD];
__device__ __align__(16) __half g_mh_u[(size_t)(NU_MAX + PAD_ROWS) * DD];
__device__ __align__(16) __half g_mh_i[(size_t)(NI_MAX + PAD_ROWS) * DD];
__device__ int g_deg[NU_MAX + NI_MAX];
__device__ int g_off[NU_MAX + NI_MAX];
__device__ int g_cur[NU_MAX + NI_MAX];
__device__ int g_bsum[256];
__device__ int g_adj_u[E_MAX];
__device__ int g_adj_i[E_MAX];
// fp16 weights, 4 cfgs. Per cfg: [32 kb][128 n][8 k] fp16 = 32768 fp16.
__device__ __align__(16) __half g_wtb[4 * 32768];

// ------- fused prologue: weight prep + fp16 table conv + deg zero ----------
__global__ void prep_all(const float* __restrict__ Wr0, const float* __restrict__ LW0,
                         const float* __restrict__ Wl0,
                         const float* __restrict__ Wr1, const float* __restrict__ LW1,
                         const float* __restrict__ Wl1,
                         const float* __restrict__ Wr2, const float* __restrict__ LW2,
                         const float* __restrict__ Wl2,
                         const float* __restrict__ Wr3, const float* __restrict__ LW3,
                         const float* __restrict__ Wl3,
                         __half* __restrict__ wtb,
                         const float* __restrict__ XA, __half* __restrict__ HA, int nA,
                         const float* __restrict__ XB, __half* __restrict__ HB, int nB,
                         int convB,
                         int* __restrict__ deg, int nTot) {
    int b = blockIdx.x;
    if (b < 128) {
        // weight prep: cfg = b>>5, kb = b&31
        int cfg = b >> 5;
        int kb = b & 31;
        const float* Wr; const float* LW; const float* Wl;
        if (cfg == 0)      { Wr = Wr0; LW = LW0; Wl = Wl0; }
        else if (cfg == 1) { Wr = Wr1; LW = LW1; Wl = Wl1; }
        else if (cfg == 2) { Wr = Wr2; LW = LW2; Wl = Wl2; }
        else               { Wr = Wr3; LW = LW3; Wl = Wl3; }
        __half* dst = wtb + cfg * 32768;
        int t = threadIdx.x;
#pragma unroll
        for (int i = 0; i < 4; ++i) {
            int e = i * 256 + t;
            int n = e >> 3, kd = e & 7;
            int k = kb * 8 + kd;
            float v;
            if (k < 128) v = Wr[n * 128 + k] + LW[n * 128 + k];
            else         v = Wl[n * 128 + (k - 128)];
            dst[kb * 1024 + e] = __float2half_rn(v);
        }
    } else if (b < 128 + convB) {
        int i = ((b - 128) * blockDim.x + threadIdx.x) * 8;
        const float* src; __half* dst;
        if (i < nA) { src = XA + i; dst = HA + i; }
        else {
            i -= nA;
            if (i >= nB) return;
            src = XB + i; dst = HB + i;
        }
        float4 v0 = *(const float4*)(src);
        float4 v1 = *(const float4*)(src + 4);
        __half2 h0 = __floats2half2_rn(v0.x, v0.y);
        __half2 h1 = __floats2half2_rn(v0.z, v0.w);
        __half2 h2 = __floats2half2_rn(v1.x, v1.y);
        __half2 h3 = __floats2half2_rn(v1.z, v1.w);
        *(uint4*)(dst) = make_uint4(*(uint32_t*)&h0, *(uint32_t*)&h1,
                                    *(uint32_t*)&h2, *(uint32_t*)&h3);
    } else {
        int i = ((b - 128 - convB) * blockDim.x + threadIdx.x) * 4;
        if (i < nTot) {
            if (i + 4 <= nTot) *(int4*)(deg + i) = make_int4(0, 0, 0, 0);
            else for (int j = i; j < nTot; ++j) deg[j] = 0;
        }
    }
}

// ---------------- CSR build (parallel scan; merged deg array) --------------
__global__ void count_deg(const int* __restrict__ iu_dst, const int* __restrict__ ui_dst,
                          int E, int nU, int* __restrict__ deg) {
    int i = blockIdx.x * blockDim.x + threadIdx.x;
    if (i < E) atomicAdd(deg + iu_dst[i], 1);
    else { i -= E; if (i < E) atomicAdd(deg + nU + ui_dst[i], 1); }
}

__global__ void scan_part(const int* __restrict__ deg, int nU, int nI,
                          int* __restrict__ off, int* __restrict__ bsum, int nbU) {
    __shared__ int warp_s[32];
    int b = blockIdx.x;
    int segbase, n, idx0;
    if (b < nbU) { segbase = 0; n = nU; idx0 = b * SCAN_B; }
    else         { segbase = nU; n = nI; idx0 = (b - nbU) * SCAN_B; }
    int i = idx0 + threadIdx.x;
    int v = (i < n) ? deg[segbase + i] : 0;
    int lane = threadIdx.x & 31, wrp = threadIdx.x >> 5;
    int inc = v;
#pragma unroll
    for (int o = 1; o < 32; o <<= 1) {
        int t = __shfl_up_sync(0xffffffffu, inc, o);
        if (lane >= o) inc += t;
    }
    if (lane == 31) warp_s[wrp] = inc;
    __syncthreads();
    if (wrp == 0) {
        int wv = warp_s[lane];
#pragma unroll
        for (int o = 1; o < 32; o <<= 1) {
            int t = __shfl_up_sync(0xffffffffu, wv, o);
            if (lane >= o) wv += t;
        }
        warp_s[lane] = wv;
    }
    __syncthreads();
    int base = (wrp > 0) ? warp_s[wrp - 1] : 0;
    int excl = base + inc - v;
    if (i < n) off[segbase + i] = excl;
    if (threadIdx.x == SCAN_B - 1) bsum[b] = base + inc;
}

__global__ void scan_top(int* __restrict__ bsum, int nbU, int nbI) {
    __shared__ int s[256];
    int t = threadIdx.x;
    int ntot = nbU + nbI;
    if (t < ntot) s[t] = bsum[t];
    __syncthreads();
    if (t == 0) {
        int acc = 0;
        for (int i = 0; i < nbU; ++i) { int tmp = s[i]; s[i] = acc; acc += tmp; }
    }
    if (t == 1) {
        int acc = 0;
        for (int i = nbU; i < ntot; ++i) { int tmp = s[i]; s[i] = acc; acc += tmp; }
    }
    __syncthreads();
    if (t < ntot) bsum[t] = s[t];
}

__global__ void scan_add(int* __restrict__ off, int* __restrict__ cur,
                         int nU, int nI, const int* __restrict__ bsum, int nbU) {
    int i = blockIdx.x * blockDim.x + threadIdx.x;
    int nTot = nU + nI;
    if (i >= nTot) return;
    int blk = (i < nU) ? (i / SCAN_B) : (nbU + (i - nU) / SCAN_B);
    int v = off[i] + bsum[blk];
    off[i] = v;
    cur[i] = v;
}

__global__ void fill_adj(const int* __restrict__ iu_src, const int* __restrict__ iu_dst,
                         const int* __restrict__ ui_src, const int* __restrict__ ui_dst,
                         int E, int nU, int* __restrict__ cur,
                         int* __restrict__ adjU, int* __restrict__ adjI) {
    int i = blockIdx.x * blockDim.x + threadIdx.x;
    if (i < E) {
        int p = atomicAdd(cur + iu_dst[i], 1);
        adjU[p] = iu_src[i];
    } else {
        i -= E;
        if (i < E) {
            int p = atomicAdd(cur + nU + ui_dst[i], 1);
            adjI[p] = ui_src[i];
        }
    }
}

// ---------------- gather MEAN (fp16; 16 lanes per dst; MLP=4) --------------
__global__ void gather_mean2(const __half* __restrict__ srcU, const int* __restrict__ adjU,
                             __half* __restrict__ outU, int nU,
                             const __half* __restrict__ srcI, const int* __restrict__ adjI,
                             __half* __restrict__ outI, int nI,
                             const int* __restrict__ off, const int* __restrict__ deg) {
    int g = (blockIdx.x * blockDim.x + threadIdx.x) >> 4;  // half-warp group
    int l16 = threadIdx.x & 15;
    const __half* feat; const int* adj; __half* out; int d, oidx;
    if (g < nU) { feat = srcU; adj = adjU; out = outU; d = g; oidx = g; }
    else {
        g -= nU;
        if (g >= nI) return;
        feat = srcI; adj = adjI; out = outI; d = g; oidx = nU + g;
    }
    int beg = __ldg(off + oidx);
    int dg = __ldg(deg + oidx);
    int end = beg + dg;
    float4 a0 = make_float4(0.f, 0.f, 0.f, 0.f);
    float4 b0 = make_float4(0.f, 0.f, 0.f, 0.f);
    float4 a1 = make_float4(0.f, 0.f, 0.f, 0.f);
    float4 b1 = make_float4(0.f, 0.f, 0.f, 0.f);
    auto addrow = [&](int s, float4& accA, float4& accB) {
        uint4 u = *(const uint4*)(feat + (size_t)s * DD + l16 * 8);
        float2 f0 = __half22float2(*(__half2*)&u.x);
        float2 f1 = __half22float2(*(__half2*)&u.y);
        float2 f2 = __half22float2(*(__half2*)&u.z);
        float2 f3 = __half22float2(*(__half2*)&u.w);
        accA.x += f0.x; accA.y += f0.y; accA.z += f1.x; accA.w += f1.y;
        accB.x += f2.x; accB.y += f2.y; accB.z += f3.x; accB.w += f3.y;
    };
    int base = beg;
    for (; base + 4 <= end; base += 4) {
        int s0 = __ldg(adj + base + 0);
        int s1 = __ldg(adj + base + 1);
        int s2 = __ldg(adj + base + 2);
        int s3 = __ldg(adj + base + 3);
        addrow(s0, a0, b0); addrow(s1, a1, b1);
        addrow(s2, a0, b0); addrow(s3, a1, b1);
    }
    for (; base < end; ++base) addrow(__ldg(adj + base), a0, b0);
    float inv = 1.0f / (float)max(dg, 1);
    a0.x = (a0.x + a1.x) * inv; a0.y = (a0.y + a1.y) * inv;
    a0.z = (a0.z + a1.z) * inv; a0.w = (a0.w + a1.w) * inv;
    b0.x = (b0.x + b1.x) * inv; b0.y = (b0.y + b1.y) * inv;
    b0.z = (b0.z + b1.z) * inv; b0.w = (b0.w + b1.w) * inv;
    __half2 o0 = __floats2half2_rn(a0.x, a0.y);
    __half2 o1 = __floats2half2_rn(a0.z, a0.w);
    __half2 o2 = __floats2half2_rn(b0.x, b0.y);
    __half2 o3 = __floats2half2_rn(b0.z, b0.w);
    *(uint4*)(out + (size_t)d * DD + l16 * 8) =
        make_uint4(*(uint32_t*)&o0, *(uint32_t*)&o1, *(uint32_t*)&o2, *(uint32_t*)&o3);
}

// ---------------- pure-fp16 fused SAGE GEMM (M=256; 3-stage pipeline) ------
__device__ __forceinline__ void ldsm4(uint32_t* r, const void* p) {
    uint32_t a = (uint32_t)__cvta_generic_to_shared(p);
    asm volatile("ldmatrix.sync.aligned.m8n8.x4.shared.b16 {%0,%1,%2,%3}, [%4];\n"
                 : "=r"(r[0]), "=r"(r[1]), "=r"(r[2]), "=r"(r[3]) : "r"(a));
}
__device__ __forceinline__ void mma16816(float* c, const uint32_t* a, const uint32_t* b) {
    asm volatile("mma.sync.aligned.m16n8k16.row.col.f32.f16.f16.f32 "
                 "{%0,%1,%2,%3}, {%4,%5,%6,%7}, {%8,%9}, {%0,%1,%2,%3};\n"
                 : "+f"(c[0]), "+f"(c[1]), "+f"(c[2]), "+f"(c[3])
                 : "r"(a[0]), "r"(a[1]), "r"(a[2]), "r"(a[3]), "r"(b[0]), "r"(b[1]));
}
__device__ __forceinline__ void cp_async16(void* smem_dst, const void* gsrc) {
    uint32_t a = (uint32_t)__cvta_generic_to_shared(smem_dst);
    asm volatile("cp.async.cg.shared.global [%0], [%1], 16;\n"
                 :: "r"(a), "l"(gsrc) : "memory");
}
#define CP_ASYNC_COMMIT() asm volatile("cp.async.commit_group;\n" ::: "memory")
#define CP_ASYNC_WAIT1()  asm volatile("cp.async.wait_group 1;\n" ::: "memory")
#define CP_ASYNC_WAIT0()  asm volatile("cp.async.wait_group 0;\n" ::: "memory")

// smem: W 3 stages x 8192 B = 24576; A 3 stages x 16384 B = 49152 (at 24576)
//       bss 128 f32 (at 73728)
#define SM_BYTES 74240

__global__ __launch_bounds__(512, 1)
void sage_gemm2(const __half* __restrict__ Xh0, const __half* __restrict__ Mh0,
                const __half* __restrict__ Wt0,
                const float* __restrict__ b1_0, const float* __restrict__ b2_0,
                float* __restrict__ out0, __half* __restrict__ outh0, int n0, int split,
                const __half* __restrict__ Xh1, const __half* __restrict__ Mh1,
                const __half* __restrict__ Wt1,
                const float* __restrict__ b1_1, const float* __restrict__ b2_1,
                float* __restrict__ out1, __half* __restrict__ outh1, int n1,
                int do_relu) {
    extern __shared__ char sm_raw[];
    __half* Wsm = (__half*)sm_raw;                    // 3 stages x 4096 halves
    __half* Asm = (__half*)(sm_raw + 24576);          // 3 stages x 8192 halves
    float* bss = (float*)(sm_raw + 73728);

    const __half* Xh; const __half* Mh; const __half* Wt;
    const float* b1; const float* b2; float* out; __half* outh; int nrows, bidx;
    if ((int)blockIdx.x < split) {
        Xh = Xh0; Mh = Mh0; Wt = Wt0; b1 = b1_0; b2 = b2_0;
        out = out0; outh = outh0; nrows = n0; bidx = blockIdx.x;
    } else {
        Xh = Xh1; Mh = Mh1; Wt = Wt1; b1 = b1_1; b2 = b2_1;
        out = out1; outh = outh1; nrows = n1; bidx = blockIdx.x - split;
    }

    const int tid = threadIdx.x;
    const int lane = tid & 31;
    const int wid = tid >> 5;
    const int m0w = (wid & 3) * 64;
    const int n0w = (wid >> 2) * 32;
    const int m0 = bidx * 256;

    const int sel = lane >> 3, lr = lane & 7;
    const int a_ro = ((sel & 1) << 3) + lr;
    const int a_kb = sel >> 1;
    const int b_ro = ((sel >> 1) << 3) + lr;
    const int b_kb = sel & 1;

    if (tid < 128) bss[tid] = b1[tid] + b2[tid];

    float acc[4][4][4];
#pragma unroll
    for (int i = 0; i < 4; ++i)
#pragma unroll
        for (int j = 0; j < 4; ++j)
#pragma unroll
            for (int q = 0; q < 4; ++q) acc[i][j][q] = 0.f;

    auto loadW = [&](int c, int st) {
        const char* sh = (const char*)(Wt + c * 4096) + tid * 16;
        char* dh = (char*)(Wsm + st * 4096) + tid * 16;
        cp_async16(dh, sh);
    };
    auto loadA = [&](int c, int st) {
        const __half* src = (c < 4) ? Xh : Mh;
        int chunk = c & 3;
#pragma unroll
        for (int h = 0; h < 2; ++h) {
            int p = tid + h * 512;
            int kb = p >> 8, row = p & 255;
            const char* s = (const char*)(src + (size_t)(m0 + row) * DD)
                            + chunk * 64 + kb * 16;
            char* d = (char*)(Asm + st * 8192) + p * 16;
            cp_async16(d, s);
        }
    };

    // 3-stage prologue: chunks 0 and 1 in flight
    loadW(0, 0); loadA(0, 0); CP_ASYNC_COMMIT();
    loadW(1, 1); loadA(1, 1); CP_ASYNC_COMMIT();

    for (int c = 0; c < 8; ++c) {
        int st = c % 3;
        CP_ASYNC_WAIT1();     // chunk c's group complete (<=1 group pending)
        __syncthreads();      // all warps see stage st; stage (c+2)%3 free
        if (c + 2 < 8) { loadW(c + 2, (c + 2) % 3); loadA(c + 2, (c + 2) % 3); }
        CP_ASYNC_COMMIT();    // commit (possibly empty) group to keep count in step
#pragma unroll
        for (int kk = 0; kk < 2; ++kk) {
            uint32_t ah[4][4], bh[2][4];
#pragma unroll
            for (int mt = 0; mt < 4; ++mt) {
                const __half* p = Asm + st * 8192 +
                    (((2 * kk + a_kb) * 256) + m0w + mt * 16 + a_ro) * 8;
                ldsm4(ah[mt], p);
            }
#pragma unroll
            for (int ng = 0; ng < 2; ++ng) {
                const __half* p = Wsm + st * 4096 +
                    (((2 * kk + b_kb) * 128) + n0w + ng * 16 + b_ro) * 8;
                ldsm4(bh[ng], p);
            }
#pragma unroll
            for (int mt = 0; mt < 4; ++mt)
#pragma unroll
                for (int nt = 0; nt < 4; ++nt)
                    mma16816(acc[mt][nt], ah[mt], &bh[nt >> 1][(nt & 1) * 2]);
        }
    }

    // epilogue: bias (+relu); layer-1 writes fp16 only, layer-2 fp32 only
#pragma unroll
    for (int mt = 0; mt < 4; ++mt) {
        int rbase = m0w + mt * 16 + (lane >> 2);
#pragma unroll
        for (int half = 0; half < 2; ++half) {
            int r = rbase + half * 8;
            if (m0 + r >= nrows) continue;
#pragma unroll
            for (int nt = 0; nt < 4; ++nt) {
                int col = n0w + nt * 8 + (lane & 3) * 2;
                float v0 = acc[mt][nt][half * 2 + 0] + bss[col];
                float v1 = acc[mt][nt][half * 2 + 1] + bss[col + 1];
                if (do_relu) {
                    v0 = fmaxf(v0, 0.f); v1 = fmaxf(v1, 0.f);
                    __half2 hv = __floats2half2_rn(v0, v1);
                    *(__half2*)(outh + (size_t)(m0 + r) * DD + col) = hv;
                } else {
                    *(float2*)(out + (size_t)(m0 + r) * DD + col) = make_float2(v0, v1);
                }
            }
        }
    }
}

// ---------------- host orchestration ----------------
extern "C" void kernel_launch(void* const* d_in, const int* in_sizes, int n_in,
                              void* d_out, int out_size) {
    const float* x_user = (const float*)d_in[0];
    const float* x_item = (const float*)d_in[1];
    const int* ui_src = (const int*)d_in[2];
    const int* ui_dst = (const int*)d_in[3];
    const int* iu_src = (const int*)d_in[4];
    const int* iu_dst = (const int*)d_in[5];
    const float* W1l_ui = (const float*)d_in[6];
    const float* b1_ui  = (const float*)d_in[7];
    const float* W1r_ui = (const float*)d_in[8];
    const float* W1l_iu = (const float*)d_in[9];
    const float* b1_iu  = (const float*)d_in[10];
    const float* W1r_iu = (const float*)d_in[11];
    const float* L1W_u  = (const float*)d_in[12];
    const float* L1b_u  = (const float*)d_in[13];
    const float* L1W_i  = (const float*)d_in[14];
    const float* L1b_i  = (const float*)d_in[15];
    const float* W2l_ui = (const float*)d_in[16];
    const float* b2_ui  = (const float*)d_in[17];
    const float* W2r_ui = (const float*)d_in[18];
    const float* W2l_iu = (const float*)d_in[19];
    const float* b2_iu  = (const float*)d_in[20];
    const float* W2r_iu = (const float*)d_in[21];
    const float* L2W_u  = (const float*)d_in[22];
    const float* L2b_u  = (const float*)d_in[23];
    const float* L2W_i  = (const float*)d_in[24];
    const float* L2b_i  = (const float*)d_in[25];

    const int NU = in_sizes[0] / DD;
    const int NI = in_sizes[1] / DD;
    const int E = in_sizes[2];

    __half *xh_u, *xh_i, *h1h_u, *h1h_i, *mh_u, *mh_i, *wtb;
    int *deg, *off, *cur, *bsum, *adj_u, *adj_i;
    cudaGetSymbolAddress((void**)&xh_u, g_xh_u);
    cudaGetSymbolAddress((void**)&xh_i, g_xh_i);
    cudaGetSymbolAddress((void**)&h1h_u, g_h1h_u);
    cudaGetSymbolAddress((void**)&h1h_i, g_h1h_i);
    cudaGetSymbolAddress((void**)&mh_u, g_mh_u);
    cudaGetSymbolAddress((void**)&mh_i, g_mh_i);
    cudaGetSymbolAddress((void**)&deg, g_deg);
    cudaGetSymbolAddress((void**)&off, g_off);
    cudaGetSymbolAddress((void**)&cur, g_cur);
    cudaGetSymbolAddress((void**)&bsum, g_bsum);
    cudaGetSymbolAddress((void**)&adj_u, g_adj_u);
    cudaGetSymbolAddress((void**)&adj_i, g_adj_i);
    cudaGetSymbolAddress((void**)&wtb, g_wtb);

    cudaFuncSetAttribute(sage_gemm2, cudaFuncAttributeMaxDynamicSharedMemorySize,
                         SM_BYTES);

    float* out_u = (float*)d_out;
    float* out_i = out_u + (size_t)NU * DD;

    int nTot = NU + NI;
    int nA = NU * DD, nB = NI * DD;
    int convB = ((nA + nB) / 8 + 255) / 256;
    int zeroB = (nTot / 4 + 255) / 256 + 1;

    // fused prologue: weights + fp16 tables + deg zero (one node)
    prep_all<<<128 + convB + zeroB, 256>>>(
        W1r_iu, L1W_u, W1l_iu, W1r_ui, L1W_i, W1l_ui,
        W2r_iu, L2W_u, W2l_iu, W2r_ui, L2W_i, W2l_ui, wtb,
        x_user, xh_u, nA, x_item, xh_i, nB, convB, deg, nTot);

    // CSR build via parallel scan (merged deg array, two segments)
    count_deg<<<(2 * E + 255) / 256, 256>>>(iu_dst, ui_dst, E, NU, deg);
    int nbU = (NU + SCAN_B - 1) / SCAN_B, nbI = (NI + SCAN_B - 1) / SCAN_B;
    scan_part<<<nbU + nbI, SCAN_B>>>(deg, NU, NI, off, bsum, nbU);
    scan_top<<<1, 256>>>(bsum, nbU, nbI);
    scan_add<<<(nTot + 255) / 256, 256>>>(off, cur, NU, NI, bsum, nbU);
    fill_adj<<<(2 * E + 255) / 256, 256>>>(iu_src, iu_dst, ui_src, ui_dst, E, NU,
                                           cur, adj_u, adj_i);

    int gblocks = (nTot * 16 + 255) / 256;
    // layer 1 aggregation: fp16 mean
    gather_mean2<<<gblocks, 256>>>(xh_i, adj_u, mh_u, NU,
                                   xh_u, adj_i, mh_i, NI, off, deg);

    int gu = (NU + 255) / 256, gi = (NI + 255) / 256;
    // layer 1 GEMMs (merged; fp16 h1 output)
    sage_gemm2<<<gu + gi, 512, SM_BYTES>>>(
        xh_u, mh_u, wtb + 0 * 32768, b1_iu, L1b_u, (float*)0, h1h_u, NU, gu,
        xh_i, mh_i, wtb + 1 * 32768, b1_ui, L1b_i, (float*)0, h1h_i, NI, 1);

    // layer 2 aggregation
    gather_mean2<<<gblocks, 256>>>(h1h_i, adj_u, mh_u, NU,
                                   h1h_u, adj_i, mh_i, NI, off, deg);

    // layer 2 GEMMs (merged; fp32 output)
    sage_gemm2<<<gu + gi, 512, SM_BYTES>>>(
        h1h_u, mh_u, wtb + 2 * 32768, b2_iu, L2b_u, out_u, (__half*)0, NU, gu,
        h1h_i, mh_i, wtb + 3 * 32768, b2_ui, L2b_i, out_i, (__half*)0, NI, 0);
}